// round 11
// baseline (speedup 1.0000x reference)
#include <cuda_runtime.h>
#include <cstdint>

// DenseRoutingMaskLayer: per-row argmax over 8 routing logits selects a
// contiguous 512-float chunk of the 4096-wide input row.
//   inputs:          [B=16384, D=4096] f32   (d_in[0])
//   routing_inputs:  [B=16384, R=8]    f32   (d_in[1])
//   out:             [B=16384, W=512]  f32
//
// Round 11: R10 with the copy widened to 256-bit accesses (sm_100 LDG.256/
// STG.256 via ld/st.global.v8.b32). Per lane: 2 loads + 2 stores instead of
// 4+4 -> half the LSU issue slots per byte. Cache policies kept from R10:
// reads evict_last, writes evict_first (both via L2::cache_hint operand).

struct VI { float v; int i; };

__device__ __forceinline__ VI vmax(VI a, VI b) {
    // b has the higher index; keep a on ties -> first occurrence wins
    VI r;
    r.v = (b.v > a.v) ? b.v : a.v;
    r.i = (b.v > a.v) ? b.i : a.i;
    return r;
}

__device__ __forceinline__ void ldg256(const float* p, uint64_t pol, uint32_t* r) {
    asm("ld.global.L2::cache_hint.v8.b32 {%0,%1,%2,%3,%4,%5,%6,%7}, [%8], %9;"
        : "=r"(r[0]), "=r"(r[1]), "=r"(r[2]), "=r"(r[3]),
          "=r"(r[4]), "=r"(r[5]), "=r"(r[6]), "=r"(r[7])
        : "l"(p), "l"(pol));
}

__device__ __forceinline__ void stg256(float* p, uint64_t pol, const uint32_t* r) {
    asm volatile(
        "st.global.L2::cache_hint.v8.b32 [%0], {%1,%2,%3,%4,%5,%6,%7,%8}, %9;"
        :: "l"(p),
           "r"(r[0]), "r"(r[1]), "r"(r[2]), "r"(r[3]),
           "r"(r[4]), "r"(r[5]), "r"(r[6]), "r"(r[7]),
           "l"(pol) : "memory");
}

__global__ __launch_bounds__(256, 6)
void dense_routing_mask_kernel(const float* __restrict__ inputs,
                               const float* __restrict__ routing,
                               float* __restrict__ out) {
    const int warp = threadIdx.x >> 5;
    const int lane = threadIdx.x & 31;
    const int row  = blockIdx.x * 8 + warp;

    // ---- argmax: all lanes load the same 8 logits (broadcast) ----
    const float4* r4 = reinterpret_cast<const float4*>(routing) + row * 2;
    const float4 a = __ldg(r4);
    const float4 b = __ldg(r4 + 1);

    VI m01 = vmax(VI{a.x, 0}, VI{a.y, 1});
    VI m23 = vmax(VI{a.z, 2}, VI{a.w, 3});
    VI m45 = vmax(VI{b.x, 4}, VI{b.y, 5});
    VI m67 = vmax(VI{b.z, 6}, VI{b.w, 7});
    VI m03 = vmax(m01, m23);
    VI m47 = vmax(m45, m67);
    const int idx = vmax(m03, m47).i;

    // cache policies: reads evict_last, writes evict_first
    uint64_t pol_r, pol_w;
    asm("createpolicy.fractional.L2::evict_last.b64 %0, 1.0;"  : "=l"(pol_r));
    asm("createpolicy.fractional.L2::evict_first.b64 %0, 1.0;" : "=l"(pol_w));

    // ---- copy the selected 512-float chunk: 2x 256-bit per lane ----
    // lane covers floats [lane*8, lane*8+8) and [256 + lane*8, ...+8)
    const float* __restrict__ src = inputs + row * 4096 + idx * 512 + lane * 8;
    float* __restrict__ dst = out + row * 512 + lane * 8;

    uint32_t t0[8], t1[8];
    ldg256(src,       pol_r, t0);
    ldg256(src + 256, pol_r, t1);

    stg256(dst,       pol_w, t0);
    stg256(dst + 256, pol_w, t1);
}

extern "C" void kernel_launch(void* const* d_in, const int* in_sizes, int n_in,
                              void* d_out, int out_size) {
    const float* inputs  = (const float*)d_in[0];
    const float* routing = (const float*)d_in[1];
    float* out = (float*)d_out;

    const int B = in_sizes[1] / 8;   // 16384
    const int blocks = B / 8;        // 2048 (8 warps per CTA, 1 row per warp)

    dense_routing_mask_kernel<<<blocks, 256>>>(inputs, routing, out);
}